// round 3
// baseline (speedup 1.0000x reference)
#include <cuda_runtime.h>
#include <math.h>

#define B_   4
#define L_   2048
#define DX_  1024
#define H_   16
#define DK_  64
#define HD_  1024      // H*DK
#define EPS_ 1e-5f

// ---------------- scratch (device globals; no allocation allowed) ----------------
__device__ float g_Qs[(size_t)B_ * L_ * HD_];
__device__ float g_Ks[(size_t)B_ * L_ * HD_];
__device__ float g_Vs[(size_t)B_ * L_ * HD_];
__device__ float g_AO[(size_t)B_ * L_ * HD_];
__device__ float g_X [(size_t)B_ * L_ * DX_];

// ---------------- generic SGEMM: C[M,N] = A[M,K] @ B[K,N] + bias -----------------
// 128x128 tile, BK=8, 256 threads, 8x8 per-thread register tile.
__global__ __launch_bounds__(256) void sgemm_bias(
    const float* __restrict__ A, const float* __restrict__ Bm,
    const float* __restrict__ bias, float* __restrict__ C,
    int M, int N, int K)
{
    __shared__ float As[8][128];   // transposed A tile: [k][m]
    __shared__ float Bs[8][128];   // [k][n]
    const int tid = threadIdx.x;
    const int tx  = tid & 15;       // 16 col-groups
    const int ty  = tid >> 4;       // 16 row-groups
    const int arow = tid >> 1, acol = (tid & 1) * 4;
    const int brow = tid >> 5, bcol = (tid & 31) * 4;

    const float* Ab = A  + (size_t)(blockIdx.y * 128) * K;
    const float* Bb = Bm + blockIdx.x * 128;

    float acc[8][8];
#pragma unroll
    for (int i = 0; i < 8; i++)
#pragma unroll
        for (int j = 0; j < 8; j++) acc[i][j] = 0.f;

    for (int k0 = 0; k0 < K; k0 += 8) {
        float4 a4 = *(const float4*)(Ab + (size_t)arow * K + k0 + acol);
        As[acol + 0][arow] = a4.x;
        As[acol + 1][arow] = a4.y;
        As[acol + 2][arow] = a4.z;
        As[acol + 3][arow] = a4.w;
        *(float4*)&Bs[brow][bcol] =
            *(const float4*)(Bb + (size_t)(k0 + brow) * N + bcol);
        __syncthreads();
#pragma unroll
        for (int k = 0; k < 8; k++) {
            float ra[8], rb[8];
            *(float4*)&ra[0] = *(float4*)&As[k][ty * 8];
            *(float4*)&ra[4] = *(float4*)&As[k][ty * 8 + 4];
            *(float4*)&rb[0] = *(float4*)&Bs[k][tx * 4];
            *(float4*)&rb[4] = *(float4*)&Bs[k][64 + tx * 4];
#pragma unroll
            for (int i = 0; i < 8; i++)
#pragma unroll
                for (int j = 0; j < 8; j++)
                    acc[i][j] = fmaf(ra[i], rb[j], acc[i][j]);
        }
        __syncthreads();
    }

#pragma unroll
    for (int i = 0; i < 8; i++) {
        const int row = blockIdx.y * 128 + ty * 8 + i;
        const int c0  = blockIdx.x * 128 + tx * 4;
        float4 o0, o1;
        o0.x = acc[i][0] + bias[c0 + 0];
        o0.y = acc[i][1] + bias[c0 + 1];
        o0.z = acc[i][2] + bias[c0 + 2];
        o0.w = acc[i][3] + bias[c0 + 3];
        o1.x = acc[i][4] + bias[c0 + 64 + 0];
        o1.y = acc[i][5] + bias[c0 + 64 + 1];
        o1.z = acc[i][6] + bias[c0 + 64 + 2];
        o1.w = acc[i][7] + bias[c0 + 64 + 3];
        *(float4*)(C + (size_t)row * N + c0)      = o0;
        *(float4*)(C + (size_t)row * N + c0 + 64) = o1;
    }
}

// ------------- scores: S[b,h,q,k] = (Qs_row . Ks_row)/8, masked -> att raw -------
// per (b,h): [2048 x 2048] = Qh[2048,64] @ Kh[2048,64]^T. 128x128 tile per block.
__global__ __launch_bounds__(256) void scores_kernel(
    const float* __restrict__ Qs, const float* __restrict__ Ks,
    const unsigned char* __restrict__ mask, float* __restrict__ att)
{
    __shared__ float Qt[16][132];   // [d][q]
    __shared__ float Kt[16][132];   // [d][k]
    const int tid = threadIdx.x;
    const int tx = tid & 15, ty = tid >> 4;
    const int bh = blockIdx.z;
    const int b = bh >> 4, h = bh & 15;
    const int q0 = blockIdx.y * 128, k0 = blockIdx.x * 128;

    const float* Qb = Qs + (size_t)b * L_ * HD_ + (size_t)h * DK_;
    const float* Kb = Ks + (size_t)b * L_ * HD_ + (size_t)h * DK_;
    const int lrow = tid >> 1, lcol = (tid & 1) * 8;

    float acc[8][8];
#pragma unroll
    for (int i = 0; i < 8; i++)
#pragma unroll
        for (int j = 0; j < 8; j++) acc[i][j] = 0.f;

#pragma unroll
    for (int c = 0; c < 4; c++) {
        const int db = c * 16;
#pragma unroll
        for (int u = 0; u < 2; u++) {
            float4 qa = *(const float4*)(Qb + (size_t)(q0 + lrow) * HD_ + db + lcol + u * 4);
            Qt[lcol + u * 4 + 0][lrow] = qa.x;
            Qt[lcol + u * 4 + 1][lrow] = qa.y;
            Qt[lcol + u * 4 + 2][lrow] = qa.z;
            Qt[lcol + u * 4 + 3][lrow] = qa.w;
            float4 ka = *(const float4*)(Kb + (size_t)(k0 + lrow) * HD_ + db + lcol + u * 4);
            Kt[lcol + u * 4 + 0][lrow] = ka.x;
            Kt[lcol + u * 4 + 1][lrow] = ka.y;
            Kt[lcol + u * 4 + 2][lrow] = ka.z;
            Kt[lcol + u * 4 + 3][lrow] = ka.w;
        }
        __syncthreads();
#pragma unroll
        for (int d = 0; d < 16; d++) {
            float ra[8], rb[8];
            *(float4*)&ra[0] = *(float4*)&Qt[d][ty * 8];
            *(float4*)&ra[4] = *(float4*)&Qt[d][ty * 8 + 4];
            *(float4*)&rb[0] = *(float4*)&Kt[d][tx * 4];
            *(float4*)&rb[4] = *(float4*)&Kt[d][64 + tx * 4];
#pragma unroll
            for (int i = 0; i < 8; i++)
#pragma unroll
                for (int j = 0; j < 8; j++)
                    acc[i][j] = fmaf(ra[i], rb[j], acc[i][j]);
        }
        __syncthreads();
    }

    float* outb = att + (size_t)(h * B_ + b) * L_ * L_;
    const unsigned char* mb = mask + (size_t)b * L_ * L_;
#pragma unroll
    for (int i = 0; i < 8; i++) {
        const int q = q0 + ty * 8 + i;
#pragma unroll
        for (int half = 0; half < 2; half++) {
            const int k = k0 + half * 64 + tx * 4;
            float4 o;
            o.x = mb[(size_t)q * L_ + k + 0] ? -INFINITY : acc[i][half * 4 + 0] * 0.125f;
            o.y = mb[(size_t)q * L_ + k + 1] ? -INFINITY : acc[i][half * 4 + 1] * 0.125f;
            o.z = mb[(size_t)q * L_ + k + 2] ? -INFINITY : acc[i][half * 4 + 2] * 0.125f;
            o.w = mb[(size_t)q * L_ + k + 3] ? -INFINITY : acc[i][half * 4 + 3] * 0.125f;
            *(float4*)(outb + (size_t)q * L_ + k) = o;
        }
    }
}

// -------------------- softmax over rows of att, in place -------------------------
__global__ __launch_bounds__(256) void softmax_kernel(float* __restrict__ att)
{
    __shared__ float red[8];
    float* row = att + (size_t)blockIdx.x * L_;
    const int tid = threadIdx.x;
    float v[8];
#pragma unroll
    for (int i = 0; i < 8; i++) v[i] = row[tid + 256 * i];

    float m = -INFINITY;
#pragma unroll
    for (int i = 0; i < 8; i++) m = fmaxf(m, v[i]);
#pragma unroll
    for (int o = 16; o; o >>= 1) m = fmaxf(m, __shfl_xor_sync(0xffffffffu, m, o));
    if ((tid & 31) == 0) red[tid >> 5] = m;
    __syncthreads();
    m = red[0];
#pragma unroll
    for (int w = 1; w < 8; w++) m = fmaxf(m, red[w]);
    __syncthreads();

    float s = 0.f;
#pragma unroll
    for (int i = 0; i < 8; i++) { v[i] = __expf(v[i] - m); s += v[i]; }
#pragma unroll
    for (int o = 16; o; o >>= 1) s += __shfl_xor_sync(0xffffffffu, s, o);
    if ((tid & 31) == 0) red[tid >> 5] = s;
    __syncthreads();
    s = red[0];
#pragma unroll
    for (int w = 1; w < 8; w++) s += red[w];

    const float inv = 1.0f / s;
#pragma unroll
    for (int i = 0; i < 8; i++) row[tid + 256 * i] = v[i] * inv;
}

// ------------- PV: AO[b,q,h,:] = P[b,h,q,:] @ Vh[2048,64] ------------------------
__global__ __launch_bounds__(256) void pv_kernel(
    const float* __restrict__ att, const float* __restrict__ Vs,
    float* __restrict__ AO)
{
    __shared__ float Pt[16][132];   // [k][q]
    __shared__ float Vt[16][68];    // [k][d]
    const int tid = threadIdx.x;
    const int tx = tid & 15, ty = tid >> 4;
    const int bh = blockIdx.y;
    const int b = bh >> 4, h = bh & 15;
    const int q0 = blockIdx.x * 128;

    const float* Pb = att + (size_t)(h * B_ + b) * L_ * L_;
    const float* Vb = Vs + (size_t)b * L_ * HD_ + (size_t)h * DK_;
    const int prow = tid >> 1, pcol = (tid & 1) * 8;
    const int vrow = tid >> 4, vcol = (tid & 15) * 4;

    float acc[8][4];
#pragma unroll
    for (int i = 0; i < 8; i++)
#pragma unroll
        for (int j = 0; j < 4; j++) acc[i][j] = 0.f;

    for (int k0 = 0; k0 < L_; k0 += 16) {
#pragma unroll
        for (int u = 0; u < 2; u++) {
            float4 p4 = *(const float4*)(Pb + (size_t)(q0 + prow) * L_ + k0 + pcol + u * 4);
            Pt[pcol + u * 4 + 0][prow] = p4.x;
            Pt[pcol + u * 4 + 1][prow] = p4.y;
            Pt[pcol + u * 4 + 2][prow] = p4.z;
            Pt[pcol + u * 4 + 3][prow] = p4.w;
        }
        *(float4*)&Vt[vrow][vcol] =
            *(const float4*)(Vb + (size_t)(k0 + vrow) * HD_ + vcol);
        __syncthreads();
#pragma unroll
        for (int k = 0; k < 16; k++) {
            float ra[8], rb[4];
            *(float4*)&ra[0] = *(float4*)&Pt[k][ty * 8];
            *(float4*)&ra[4] = *(float4*)&Pt[k][ty * 8 + 4];
            *(float4*)&rb[0] = *(float4*)&Vt[k][tx * 4];
#pragma unroll
            for (int i = 0; i < 8; i++)
#pragma unroll
                for (int j = 0; j < 4; j++)
                    acc[i][j] = fmaf(ra[i], rb[j], acc[i][j]);
        }
        __syncthreads();
    }

#pragma unroll
    for (int i = 0; i < 8; i++) {
        const int q = q0 + ty * 8 + i;
        float4 o; o.x = acc[i][0]; o.y = acc[i][1]; o.z = acc[i][2]; o.w = acc[i][3];
        *(float4*)(AO + (size_t)(b * L_ + q) * HD_ + h * DK_ + tx * 4) = o;
    }
}

// ---------------- residual + LayerNorm: y = LN(X + Q)*gamma + beta ---------------
__global__ __launch_bounds__(256) void ln_kernel(
    const float* __restrict__ X, const float* __restrict__ Qin,
    const float* __restrict__ gamma, const float* __restrict__ beta,
    float* __restrict__ y)
{
    __shared__ float red[8];
    const int row = blockIdx.x;
    const int tid = threadIdx.x;
    const float* xr = X + (size_t)row * DX_;
    const float* qr = Qin + (size_t)row * DX_;

    float x[4];
#pragma unroll
    for (int i = 0; i < 4; i++) x[i] = xr[tid + 256 * i] + qr[tid + 256 * i];

    float s = x[0] + x[1] + x[2] + x[3];
#pragma unroll
    for (int o = 16; o; o >>= 1) s += __shfl_xor_sync(0xffffffffu, s, o);
    if ((tid & 31) == 0) red[tid >> 5] = s;
    __syncthreads();
    s = red[0];
#pragma unroll
    for (int w = 1; w < 8; w++) s += red[w];
    const float mu = s * (1.0f / DX_);
    __syncthreads();

    float vs = 0.f;
#pragma unroll
    for (int i = 0; i < 4; i++) { float d = x[i] - mu; vs += d * d; }
#pragma unroll
    for (int o = 16; o; o >>= 1) vs += __shfl_xor_sync(0xffffffffu, vs, o);
    if ((tid & 31) == 0) red[tid >> 5] = vs;
    __syncthreads();
    vs = red[0];
#pragma unroll
    for (int w = 1; w < 8; w++) vs += red[w];
    const float var = vs * (1.0f / DX_);
    const float rs = rsqrtf(var + EPS_);

#pragma unroll
    for (int i = 0; i < 4; i++) {
        const int c = tid + 256 * i;
        y[(size_t)row * DX_ + c] = (x[i] - mu) * rs * gamma[c] + beta[c];
    }
}

// --------------------------------- launch ---------------------------------------
extern "C" void kernel_launch(void* const* d_in, const int* in_sizes, int n_in,
                              void* d_out, int out_size)
{
    const float* Q  = (const float*)d_in[0];
    const float* K  = (const float*)d_in[1];
    const float* V  = (const float*)d_in[2];
    const unsigned char* mask = (const unsigned char*)d_in[3];
    const float* Wq = (const float*)d_in[4];
    const float* bq = (const float*)d_in[5];
    const float* Wk = (const float*)d_in[6];
    const float* bk = (const float*)d_in[7];
    const float* Wv = (const float*)d_in[8];
    const float* bv = (const float*)d_in[9];
    const float* Wo = (const float*)d_in[10];
    const float* bo = (const float*)d_in[11];
    const float* gamma = (const float*)d_in[12];
    const float* beta  = (const float*)d_in[13];

    float* y   = (float*)d_out;
    float* att = (float*)d_out + (size_t)B_ * L_ * DX_;

    static float *pQs = nullptr, *pKs = nullptr, *pVs = nullptr, *pAO = nullptr, *pX = nullptr;
    if (!pQs) {
        cudaGetSymbolAddress((void**)&pQs, g_Qs);
        cudaGetSymbolAddress((void**)&pKs, g_Ks);
        cudaGetSymbolAddress((void**)&pVs, g_Vs);
        cudaGetSymbolAddress((void**)&pAO, g_AO);
        cudaGetSymbolAddress((void**)&pX,  g_X);
    }

    const dim3 gProj(HD_ / 128, (B_ * L_) / 128);   // (8, 64)

    sgemm_bias<<<gProj, 256>>>(Q, Wq, bq, pQs, B_ * L_, HD_, DX_);
    sgemm_bias<<<gProj, 256>>>(K, Wk, bk, pKs, B_ * L_, HD_, DX_);
    sgemm_bias<<<gProj, 256>>>(V, Wv, bv, pVs, B_ * L_, HD_, DX_);

    scores_kernel<<<dim3(L_ / 128, L_ / 128, B_ * H_), 256>>>(pQs, pKs, mask, att);
    softmax_kernel<<<B_ * H_ * L_, 256>>>(att);
    pv_kernel<<<dim3(L_ / 128, B_ * H_), 256>>>(att, pVs, pAO);

    sgemm_bias<<<gProj, 256>>>(pAO, Wo, bo, pX, B_ * L_, DX_, HD_);
    ln_kernel<<<B_ * L_, 256>>>(pX, Q, gamma, beta, y);
}

// round 4
// speedup vs baseline: 1.5520x; 1.5520x over previous
#include <cuda_runtime.h>
#include <math.h>

#define B_   4
#define L_   2048
#define DX_  1024
#define H_   16
#define DK_  64
#define HD_  1024      // H*DK
#define EPS_ 1e-5f

// ---------------- scratch (device globals; no allocation allowed) ----------------
__device__ float g_Qs[(size_t)B_ * L_ * HD_];
__device__ float g_Ks[(size_t)B_ * L_ * HD_];
__device__ float g_Vs[(size_t)B_ * L_ * HD_];
__device__ float g_AO[(size_t)B_ * L_ * HD_];
__device__ float g_X [(size_t)B_ * L_ * DX_];

// ---------------- tf32 helpers ---------------------------------------------------
__device__ __forceinline__ unsigned f2tf(float x) {
    unsigned r; asm("cvt.rna.tf32.f32 %0, %1;" : "=r"(r) : "f"(x)); return r;
}

__device__ __forceinline__ void mma8(float* d, const unsigned* a, const unsigned* b) {
    asm volatile(
        "mma.sync.aligned.m16n8k8.row.col.f32.tf32.tf32.f32 "
        "{%0,%1,%2,%3},{%4,%5,%6,%7},{%8,%9},{%0,%1,%2,%3};"
        : "+f"(d[0]), "+f"(d[1]), "+f"(d[2]), "+f"(d[3])
        : "r"(a[0]), "r"(a[1]), "r"(a[2]), "r"(a[3]), "r"(b[0]), "r"(b[1]));
}

// ================= TF32 SGEMM: C[M,N] = A[M,K] @ B[K,N] + bias ===================
// 128x128 tile, BK=16, 256 threads (8 warps, 4x2), warp tile 32x64.
__global__ __launch_bounds__(256) void sgemm_tf32(
    const float* __restrict__ A, const float* __restrict__ Bm,
    const float* __restrict__ bias, float* __restrict__ C,
    int M, int N, int K)
{
    __shared__ unsigned As[128][20];   // [m][k], stride 20 -> conflict-free frags
    __shared__ unsigned Bs[16][136];   // [k][n], stride 136 -> conflict-free frags
    const int tid  = threadIdx.x;
    const int lane = tid & 31, warp = tid >> 5;
    const int wr = warp >> 1, wc = warp & 1;
    const int gm = lane >> 2, kq = lane & 3;

    const float* Ab = A  + (size_t)(blockIdx.y * 128) * K;
    const float* Bb = Bm + blockIdx.x * 128;

    const int arow = tid >> 1,  acol = (tid & 1) * 8;
    const int brow = tid >> 4,  bcol = (tid & 15) * 8;

    float acc[2][8][4];
#pragma unroll
    for (int i = 0; i < 2; i++)
#pragma unroll
        for (int j = 0; j < 8; j++)
#pragma unroll
            for (int r = 0; r < 4; r++) acc[i][j][r] = 0.f;

    for (int k0 = 0; k0 < K; k0 += 16) {
        float4 a0 = *(const float4*)(Ab + (size_t)arow * K + k0 + acol);
        float4 a1 = *(const float4*)(Ab + (size_t)arow * K + k0 + acol + 4);
        *(uint4*)&As[arow][acol]     = make_uint4(f2tf(a0.x), f2tf(a0.y), f2tf(a0.z), f2tf(a0.w));
        *(uint4*)&As[arow][acol + 4] = make_uint4(f2tf(a1.x), f2tf(a1.y), f2tf(a1.z), f2tf(a1.w));
        float4 b0 = *(const float4*)(Bb + (size_t)(k0 + brow) * N + bcol);
        float4 b1 = *(const float4*)(Bb + (size_t)(k0 + brow) * N + bcol + 4);
        *(uint4*)&Bs[brow][bcol]     = make_uint4(f2tf(b0.x), f2tf(b0.y), f2tf(b0.z), f2tf(b0.w));
        *(uint4*)&Bs[brow][bcol + 4] = make_uint4(f2tf(b1.x), f2tf(b1.y), f2tf(b1.z), f2tf(b1.w));
        __syncthreads();
#pragma unroll
        for (int kk = 0; kk < 16; kk += 8) {
            unsigned af[2][4], bf[8][2];
#pragma unroll
            for (int i = 0; i < 2; i++) {
                const int mb = wr * 32 + i * 16;
                af[i][0] = As[mb + gm    ][kk + kq];
                af[i][1] = As[mb + gm + 8][kk + kq];
                af[i][2] = As[mb + gm    ][kk + kq + 4];
                af[i][3] = As[mb + gm + 8][kk + kq + 4];
            }
#pragma unroll
            for (int j = 0; j < 8; j++) {
                const int nb = wc * 64 + j * 8;
                bf[j][0] = Bs[kk + kq    ][nb + gm];
                bf[j][1] = Bs[kk + kq + 4][nb + gm];
            }
#pragma unroll
            for (int i = 0; i < 2; i++)
#pragma unroll
                for (int j = 0; j < 8; j++) mma8(acc[i][j], af[i], bf[j]);
        }
        __syncthreads();
    }

#pragma unroll
    for (int i = 0; i < 2; i++)
#pragma unroll
        for (int j = 0; j < 8; j++) {
            const int row = blockIdx.y * 128 + wr * 32 + i * 16 + gm;
            const int col = blockIdx.x * 128 + wc * 64 + j * 8 + kq * 2;
            float2 bv = *(const float2*)(bias + col);
            float2 o0, o1;
            o0.x = acc[i][j][0] + bv.x; o0.y = acc[i][j][1] + bv.y;
            o1.x = acc[i][j][2] + bv.x; o1.y = acc[i][j][3] + bv.y;
            *(float2*)(C + (size_t)row * N + col)       = o0;
            *(float2*)(C + (size_t)(row + 8) * N + col) = o1;
        }
}

// ============ scores: S[b,h,q,k] = (Qh @ Kh^T)/8, masked ========================
// per (b,h) block computes a 128x128 tile; K(=64) split into 2 chunks of 32.
__global__ __launch_bounds__(256) void scores_tf32(
    const float* __restrict__ Qs, const float* __restrict__ Ks,
    const unsigned char* __restrict__ mask, float* __restrict__ att)
{
    __shared__ unsigned Qt[128][36];   // [q][k-chunk]
    __shared__ unsigned Kt[128][36];   // [k-row][k-chunk]  (B col-major = K row-major)
    const int tid  = threadIdx.x;
    const int lane = tid & 31, warp = tid >> 5;
    const int wr = warp >> 1, wc = warp & 1;
    const int gm = lane >> 2, kq = lane & 3;
    const int bh = blockIdx.z;
    const int b = bh >> 4, h = bh & 15;
    const int q0 = blockIdx.y * 128, n0 = blockIdx.x * 128;

    const float* Qb = Qs + (size_t)b * L_ * HD_ + (size_t)h * DK_;
    const float* Kb = Ks + (size_t)b * L_ * HD_ + (size_t)h * DK_;
    const int lrow = tid >> 1, lcb = (tid & 1) * 16;

    float acc[2][8][4];
#pragma unroll
    for (int i = 0; i < 2; i++)
#pragma unroll
        for (int j = 0; j < 8; j++)
#pragma unroll
            for (int r = 0; r < 4; r++) acc[i][j][r] = 0.f;

#pragma unroll
    for (int c = 0; c < 2; c++) {
        const int kb = c * 32;
#pragma unroll
        for (int u = 0; u < 4; u++) {
            float4 q4 = *(const float4*)(Qb + (size_t)(q0 + lrow) * HD_ + kb + lcb + u * 4);
            *(uint4*)&Qt[lrow][lcb + u * 4] =
                make_uint4(f2tf(q4.x), f2tf(q4.y), f2tf(q4.z), f2tf(q4.w));
            float4 k4 = *(const float4*)(Kb + (size_t)(n0 + lrow) * HD_ + kb + lcb + u * 4);
            *(uint4*)&Kt[lrow][lcb + u * 4] =
                make_uint4(f2tf(k4.x), f2tf(k4.y), f2tf(k4.z), f2tf(k4.w));
        }
        __syncthreads();
#pragma unroll
        for (int kk = 0; kk < 32; kk += 8) {
            unsigned af[2][4], bf[8][2];
#pragma unroll
            for (int i = 0; i < 2; i++) {
                const int mb = wr * 32 + i * 16;
                af[i][0] = Qt[mb + gm    ][kk + kq];
                af[i][1] = Qt[mb + gm + 8][kk + kq];
                af[i][2] = Qt[mb + gm    ][kk + kq + 4];
                af[i][3] = Qt[mb + gm + 8][kk + kq + 4];
            }
#pragma unroll
            for (int j = 0; j < 8; j++) {
                const int nb = wc * 64 + j * 8;
                bf[j][0] = Kt[nb + gm][kk + kq];
                bf[j][1] = Kt[nb + gm][kk + kq + 4];
            }
#pragma unroll
            for (int i = 0; i < 2; i++)
#pragma unroll
                for (int j = 0; j < 8; j++) mma8(acc[i][j], af[i], bf[j]);
        }
        __syncthreads();
    }

    float* outb = att + (size_t)(h * B_ + b) * L_ * L_;
    const unsigned char* mb = mask + (size_t)b * L_ * L_;
#pragma unroll
    for (int i = 0; i < 2; i++)
#pragma unroll
        for (int j = 0; j < 8; j++) {
            const int q = q0 + wr * 32 + i * 16 + gm;
            const int k = n0 + wc * 64 + j * 8 + kq * 2;
            float2 o0, o1;
            o0.x = mb[(size_t)q * L_ + k]           ? -INFINITY : acc[i][j][0] * 0.125f;
            o0.y = mb[(size_t)q * L_ + k + 1]       ? -INFINITY : acc[i][j][1] * 0.125f;
            o1.x = mb[(size_t)(q + 8) * L_ + k]     ? -INFINITY : acc[i][j][2] * 0.125f;
            o1.y = mb[(size_t)(q + 8) * L_ + k + 1] ? -INFINITY : acc[i][j][3] * 0.125f;
            *(float2*)(outb + (size_t)q * L_ + k)       = o0;
            *(float2*)(outb + (size_t)(q + 8) * L_ + k) = o1;
        }
}

// -------------------- softmax over rows of att, in place -------------------------
__global__ __launch_bounds__(256) void softmax_kernel(float* __restrict__ att)
{
    __shared__ float red[8];
    float* row = att + (size_t)blockIdx.x * L_;
    const int tid = threadIdx.x;
    float v[8];
#pragma unroll
    for (int i = 0; i < 8; i++) v[i] = row[tid + 256 * i];

    float m = -INFINITY;
#pragma unroll
    for (int i = 0; i < 8; i++) m = fmaxf(m, v[i]);
#pragma unroll
    for (int o = 16; o; o >>= 1) m = fmaxf(m, __shfl_xor_sync(0xffffffffu, m, o));
    if ((tid & 31) == 0) red[tid >> 5] = m;
    __syncthreads();
    m = red[0];
#pragma unroll
    for (int w = 1; w < 8; w++) m = fmaxf(m, red[w]);
    __syncthreads();

    float s = 0.f;
#pragma unroll
    for (int i = 0; i < 8; i++) { v[i] = __expf(v[i] - m); s += v[i]; }
#pragma unroll
    for (int o = 16; o; o >>= 1) s += __shfl_xor_sync(0xffffffffu, s, o);
    if ((tid & 31) == 0) red[tid >> 5] = s;
    __syncthreads();
    s = red[0];
#pragma unroll
    for (int w = 1; w < 8; w++) s += red[w];

    const float inv = 1.0f / s;
#pragma unroll
    for (int i = 0; i < 8; i++) row[tid + 256 * i] = v[i] * inv;
}

// ============ PV: AO[b,q,h,:] = P[b,h,q,:] @ Vh[2048,64] ========================
// block: 128 q-rows x 64 cols. 8 warps (4x2), warp tile 32x32. BK=32.
__global__ __launch_bounds__(256) void pv_tf32(
    const float* __restrict__ att, const float* __restrict__ Vs,
    float* __restrict__ AO)
{
    __shared__ unsigned Pt[128][36];   // [q][k]
    __shared__ unsigned Vt[32][72];    // [k][n], stride 72 -> conflict-free frags
    const int tid  = threadIdx.x;
    const int lane = tid & 31, warp = tid >> 5;
    const int wr = warp >> 1, wc = warp & 1;
    const int gm = lane >> 2, kq = lane & 3;
    const int bh = blockIdx.y;
    const int b = bh >> 4, h = bh & 15;
    const int q0 = blockIdx.x * 128;

    const float* Pb = att + (size_t)(h * B_ + b) * L_ * L_;
    const float* Vb = Vs + (size_t)b * L_ * HD_ + (size_t)h * DK_;
    const int prow = tid >> 1, pcb = (tid & 1) * 16;
    const int vrow = tid >> 3, vcol = (tid & 7) * 8;

    float acc[2][4][4];
#pragma unroll
    for (int i = 0; i < 2; i++)
#pragma unroll
        for (int j = 0; j < 4; j++)
#pragma unroll
            for (int r = 0; r < 4; r++) acc[i][j][r] = 0.f;

    for (int k0 = 0; k0 < L_; k0 += 32) {
#pragma unroll
        for (int u = 0; u < 4; u++) {
            float4 p4 = *(const float4*)(Pb + (size_t)(q0 + prow) * L_ + k0 + pcb + u * 4);
            *(uint4*)&Pt[prow][pcb + u * 4] =
                make_uint4(f2tf(p4.x), f2tf(p4.y), f2tf(p4.z), f2tf(p4.w));
        }
#pragma unroll
        for (int u = 0; u < 2; u++) {
            float4 v4 = *(const float4*)(Vb + (size_t)(k0 + vrow) * HD_ + vcol + u * 4);
            *(uint4*)&Vt[vrow][vcol + u * 4] =
                make_uint4(f2tf(v4.x), f2tf(v4.y), f2tf(v4.z), f2tf(v4.w));
        }
        __syncthreads();
#pragma unroll
        for (int kk = 0; kk < 32; kk += 8) {
            unsigned af[2][4], bf[4][2];
#pragma unroll
            for (int i = 0; i < 2; i++) {
                const int mb = wr * 32 + i * 16;
                af[i][0] = Pt[mb + gm    ][kk + kq];
                af[i][1] = Pt[mb + gm + 8][kk + kq];
                af[i][2] = Pt[mb + gm    ][kk + kq + 4];
                af[i][3] = Pt[mb + gm + 8][kk + kq + 4];
            }
#pragma unroll
            for (int j = 0; j < 4; j++) {
                const int nb = wc * 32 + j * 8;
                bf[j][0] = Vt[kk + kq    ][nb + gm];
                bf[j][1] = Vt[kk + kq + 4][nb + gm];
            }
#pragma unroll
            for (int i = 0; i < 2; i++)
#pragma unroll
                for (int j = 0; j < 4; j++) mma8(acc[i][j], af[i], bf[j]);
        }
        __syncthreads();
    }

#pragma unroll
    for (int i = 0; i < 2; i++)
#pragma unroll
        for (int j = 0; j < 4; j++) {
            const int q = q0 + wr * 32 + i * 16 + gm;
            const int col = wc * 32 + j * 8 + kq * 2;
            float2 o0, o1;
            o0.x = acc[i][j][0]; o0.y = acc[i][j][1];
            o1.x = acc[i][j][2]; o1.y = acc[i][j][3];
            *(float2*)(AO + (size_t)(b * L_ + q) * HD_ + h * DK_ + col)       = o0;
            *(float2*)(AO + (size_t)(b * L_ + q + 8) * HD_ + h * DK_ + col)  = o1;
        }
}

// ---------------- residual + LayerNorm: y = LN(X + Q)*gamma + beta ---------------
__global__ __launch_bounds__(256) void ln_kernel(
    const float* __restrict__ X, const float* __restrict__ Qin,
    const float* __restrict__ gamma, const float* __restrict__ beta,
    float* __restrict__ y)
{
    __shared__ float red[8];
    const int row = blockIdx.x;
    const int tid = threadIdx.x;
    const float* xr = X + (size_t)row * DX_;
    const float* qr = Qin + (size_t)row * DX_;

    float x[4];
#pragma unroll
    for (int i = 0; i < 4; i++) x[i] = xr[tid + 256 * i] + qr[tid + 256 * i];

    float s = x[0] + x[1] + x[2] + x[3];
#pragma unroll
    for (int o = 16; o; o >>= 1) s += __shfl_xor_sync(0xffffffffu, s, o);
    if ((tid & 31) == 0) red[tid >> 5] = s;
    __syncthreads();
    s = red[0];
#pragma unroll
    for (int w = 1; w < 8; w++) s += red[w];
    const float mu = s * (1.0f / DX_);
    __syncthreads();

    float vs = 0.f;
#pragma unroll
    for (int i = 0; i < 4; i++) { float d = x[i] - mu; vs += d * d; }
#pragma unroll
    for (int o = 16; o; o >>= 1) vs += __shfl_xor_sync(0xffffffffu, vs, o);
    if ((tid & 31) == 0) red[tid >> 5] = vs;
    __syncthreads();
    vs = red[0];
#pragma unroll
    for (int w = 1; w < 8; w++) vs += red[w];
    const float var = vs * (1.0f / DX_);
    const float rs = rsqrtf(var + EPS_);

#pragma unroll
    for (int i = 0; i < 4; i++) {
        const int c = tid + 256 * i;
        y[(size_t)row * DX_ + c] = (x[i] - mu) * rs * gamma[c] + beta[c];
    }
}

// --------------------------------- launch ---------------------------------------
extern "C" void kernel_launch(void* const* d_in, const int* in_sizes, int n_in,
                              void* d_out, int out_size)
{
    const float* Q  = (const float*)d_in[0];
    const float* K  = (const float*)d_in[1];
    const float* V  = (const float*)d_in[2];
    const unsigned char* mask = (const unsigned char*)d_in[3];
    const float* Wq = (const float*)d_in[4];
    const float* bq = (const float*)d_in[5];
    const float* Wk = (const float*)d_in[6];
    const float* bk = (const float*)d_in[7];
    const float* Wv = (const float*)d_in[8];
    const float* bv = (const float*)d_in[9];
    const float* Wo = (const float*)d_in[10];
    const float* bo = (const float*)d_in[11];
    const float* gamma = (const float*)d_in[12];
    const float* beta  = (const float*)d_in[13];

    float* y   = (float*)d_out;
    float* att = (float*)d_out + (size_t)B_ * L_ * DX_;

    static float *pQs = nullptr, *pKs = nullptr, *pVs = nullptr, *pAO = nullptr, *pX = nullptr;
    if (!pQs) {
        cudaGetSymbolAddress((void**)&pQs, g_Qs);
        cudaGetSymbolAddress((void**)&pKs, g_Ks);
        cudaGetSymbolAddress((void**)&pVs, g_Vs);
        cudaGetSymbolAddress((void**)&pAO, g_AO);
        cudaGetSymbolAddress((void**)&pX,  g_X);
    }

    const dim3 gProj(HD_ / 128, (B_ * L_) / 128);   // (8, 64)

    sgemm_tf32<<<gProj, 256>>>(Q, Wq, bq, pQs, B_ * L_, HD_, DX_);
    sgemm_tf32<<<gProj, 256>>>(K, Wk, bk, pKs, B_ * L_, HD_, DX_);
    sgemm_tf32<<<gProj, 256>>>(V, Wv, bv, pVs, B_ * L_, HD_, DX_);

    scores_tf32<<<dim3(L_ / 128, L_ / 128, B_ * H_), 256>>>(pQs, pKs, mask, att);
    softmax_kernel<<<B_ * H_ * L_, 256>>>(att);
    pv_tf32<<<dim3(L_ / 128, B_ * H_), 256>>>(att, pVs, pAO);

    sgemm_tf32<<<gProj, 256>>>(pAO, Wo, bo, pX, B_ * L_, DX_, HD_);
    ln_kernel<<<B_ * L_, 256>>>(pX, Q, gamma, beta, y);
}

// round 5
// speedup vs baseline: 1.7830x; 1.1488x over previous
#include <cuda_runtime.h>
#include <math.h>

#define B_   4
#define L_   2048
#define DX_  1024
#define H_   16
#define DK_  64
#define HD_  1024      // H*DK
#define EPS_ 1e-5f

// ---------------- scratch (device globals; no allocation allowed) ----------------
__device__ float g_Qs[(size_t)B_ * L_ * HD_];
__device__ float g_Ks[(size_t)B_ * L_ * HD_];
__device__ float g_Vs[(size_t)B_ * L_ * HD_];
__device__ float g_AO[(size_t)B_ * L_ * HD_];
__device__ float g_X [(size_t)B_ * L_ * DX_];
// tf32-prerounded copies of raw inputs
__device__ float g_rQ[(size_t)B_ * L_ * DX_];
__device__ float g_rK[(size_t)B_ * L_ * DX_];
__device__ float g_rV[(size_t)B_ * L_ * DX_];
__device__ float g_rWq[(size_t)DX_ * HD_];
__device__ float g_rWk[(size_t)DX_ * HD_];
__device__ float g_rWv[(size_t)DX_ * HD_];
__device__ float g_rWo[(size_t)HD_ * DX_];

// ---------------- tf32 / cp.async helpers ----------------------------------------
__device__ __forceinline__ unsigned f2tf(float x) {
    unsigned r; asm("cvt.rna.tf32.f32 %0, %1;" : "=r"(r) : "f"(x)); return r;
}
__device__ __forceinline__ float rndtf(float x) { return __uint_as_float(f2tf(x)); }

__device__ __forceinline__ void cp16(unsigned* s, const float* g) {
    unsigned a = (unsigned)__cvta_generic_to_shared(s);
    asm volatile("cp.async.cg.shared.global [%0], [%1], 16;" :: "r"(a), "l"(g));
}
__device__ __forceinline__ void cpcommit() {
    asm volatile("cp.async.commit_group;" ::: "memory");
}
__device__ __forceinline__ void cpwait0() {
    asm volatile("cp.async.wait_group 0;" ::: "memory");
}

__device__ __forceinline__ void mma8(float* d, const unsigned* a, const unsigned* b) {
    asm volatile(
        "mma.sync.aligned.m16n8k8.row.col.f32.tf32.tf32.f32 "
        "{%0,%1,%2,%3},{%4,%5,%6,%7},{%8,%9},{%0,%1,%2,%3};"
        : "+f"(d[0]), "+f"(d[1]), "+f"(d[2]), "+f"(d[3])
        : "r"(a[0]), "r"(a[1]), "r"(a[2]), "r"(a[3]), "r"(b[0]), "r"(b[1]));
}

// ---------------- pre-round inputs to tf32 ---------------------------------------
__global__ __launch_bounds__(256) void round_tf32(
    const float4* __restrict__ in, float4* __restrict__ out, int n4)
{
    int i = blockIdx.x * blockDim.x + threadIdx.x;
    if (i < n4) {
        float4 v = in[i];
        v.x = rndtf(v.x); v.y = rndtf(v.y); v.z = rndtf(v.z); v.w = rndtf(v.w);
        out[i] = v;
    }
}

// ================= TF32 SGEMM: C[M,N] = A[M,K] @ B[K,N] + bias ===================
// inputs already tf32-rounded. 128x128 tile, BK=16, cp.async double buffered.
template<bool ROUND_OUT>
__global__ __launch_bounds__(256, 2) void sgemm_tf32(
    const float* __restrict__ A, const float* __restrict__ Bm,
    const float* __restrict__ bias, float* __restrict__ C,
    int M, int N, int K)
{
    __shared__ unsigned As[2][128][20];
    __shared__ unsigned Bs[2][16][136];
    const int tid  = threadIdx.x;
    const int lane = tid & 31, warp = tid >> 5;
    const int wr = warp >> 1, wc = warp & 1;
    const int gm = lane >> 2, kq = lane & 3;

    const float* Ab = A  + (size_t)(blockIdx.y * 128) * K;
    const float* Bb = Bm + blockIdx.x * 128;
    const int arow = tid >> 1,  acol = (tid & 1) * 8;
    const int brow = tid >> 4,  bcol = (tid & 15) * 8;

    float acc[2][8][4];
#pragma unroll
    for (int i = 0; i < 2; i++)
#pragma unroll
        for (int j = 0; j < 8; j++)
#pragma unroll
            for (int r = 0; r < 4; r++) acc[i][j][r] = 0.f;

    auto load = [&](int buf, int k0) {
        cp16(&As[buf][arow][acol],     Ab + (size_t)arow * K + k0 + acol);
        cp16(&As[buf][arow][acol + 4], Ab + (size_t)arow * K + k0 + acol + 4);
        cp16(&Bs[buf][brow][bcol],     Bb + (size_t)(k0 + brow) * N + bcol);
        cp16(&Bs[buf][brow][bcol + 4], Bb + (size_t)(k0 + brow) * N + bcol + 4);
    };

    load(0, 0); cpcommit();
    int buf = 0;
    for (int k0 = 0; k0 < K; k0 += 16) {
        cpwait0();
        __syncthreads();
        if (k0 + 16 < K) { load(buf ^ 1, k0 + 16); cpcommit(); }
#pragma unroll
        for (int kk = 0; kk < 16; kk += 8) {
            unsigned af[2][4], bf[8][2];
#pragma unroll
            for (int i = 0; i < 2; i++) {
                const int mb = wr * 32 + i * 16;
                af[i][0] = As[buf][mb + gm    ][kk + kq];
                af[i][1] = As[buf][mb + gm + 8][kk + kq];
                af[i][2] = As[buf][mb + gm    ][kk + kq + 4];
                af[i][3] = As[buf][mb + gm + 8][kk + kq + 4];
            }
#pragma unroll
            for (int j = 0; j < 8; j++) {
                const int nb = wc * 64 + j * 8;
                bf[j][0] = Bs[buf][kk + kq    ][nb + gm];
                bf[j][1] = Bs[buf][kk + kq + 4][nb + gm];
            }
#pragma unroll
            for (int i = 0; i < 2; i++)
#pragma unroll
                for (int j = 0; j < 8; j++) mma8(acc[i][j], af[i], bf[j]);
        }
        __syncthreads();
        buf ^= 1;
    }

#pragma unroll
    for (int i = 0; i < 2; i++)
#pragma unroll
        for (int j = 0; j < 8; j++) {
            const int row = blockIdx.y * 128 + wr * 32 + i * 16 + gm;
            const int col = blockIdx.x * 128 + wc * 64 + j * 8 + kq * 2;
            float2 bv = *(const float2*)(bias + col);
            float2 o0, o1;
            o0.x = acc[i][j][0] + bv.x; o0.y = acc[i][j][1] + bv.y;
            o1.x = acc[i][j][2] + bv.x; o1.y = acc[i][j][3] + bv.y;
            if (ROUND_OUT) {
                o0.x = rndtf(o0.x); o0.y = rndtf(o0.y);
                o1.x = rndtf(o1.x); o1.y = rndtf(o1.y);
            }
            *(float2*)(C + (size_t)row * N + col)       = o0;
            *(float2*)(C + (size_t)(row + 8) * N + col) = o1;
        }
}

// ============ scores: S[b,h,q,k] = (Qh @ Kh^T)/8, masked ========================
// inputs pre-rounded tf32. Full DK=64 loaded in one shot; single sync; 8 mma steps.
#define SCS 68
__global__ __launch_bounds__(256, 2) void scores_tf32(
    const float* __restrict__ Qs, const float* __restrict__ Ks,
    const unsigned char* __restrict__ mask, float* __restrict__ att)
{
    extern __shared__ unsigned sm[];
    unsigned (*Qt)[SCS] = (unsigned(*)[SCS])sm;
    unsigned (*Kt)[SCS] = (unsigned(*)[SCS])(sm + 128 * SCS);

    const int tid  = threadIdx.x;
    const int lane = tid & 31, warp = tid >> 5;
    const int wr = warp >> 1, wc = warp & 1;
    const int gm = lane >> 2, kq = lane & 3;
    const int bh = blockIdx.z;
    const int b = bh >> 4, h = bh & 15;
    const int q0 = blockIdx.y * 128, n0 = blockIdx.x * 128;

    const float* Qb = Qs + (size_t)b * L_ * HD_ + (size_t)h * DK_;
    const float* Kb = Ks + (size_t)b * L_ * HD_ + (size_t)h * DK_;
    const int lrow = tid >> 1, lcb = (tid & 1) * 32;

#pragma unroll
    for (int u = 0; u < 8; u++) {
        cp16(&Qt[lrow][lcb + u * 4], Qb + (size_t)(q0 + lrow) * HD_ + lcb + u * 4);
        cp16(&Kt[lrow][lcb + u * 4], Kb + (size_t)(n0 + lrow) * HD_ + lcb + u * 4);
    }
    cpcommit();

    float acc[2][8][4];
#pragma unroll
    for (int i = 0; i < 2; i++)
#pragma unroll
        for (int j = 0; j < 8; j++)
#pragma unroll
            for (int r = 0; r < 4; r++) acc[i][j][r] = 0.f;

    cpwait0();
    __syncthreads();

#pragma unroll
    for (int kk = 0; kk < 64; kk += 8) {
        unsigned af[2][4], bf[8][2];
#pragma unroll
        for (int i = 0; i < 2; i++) {
            const int mb = wr * 32 + i * 16;
            af[i][0] = Qt[mb + gm    ][kk + kq];
            af[i][1] = Qt[mb + gm + 8][kk + kq];
            af[i][2] = Qt[mb + gm    ][kk + kq + 4];
            af[i][3] = Qt[mb + gm + 8][kk + kq + 4];
        }
#pragma unroll
        for (int j = 0; j < 8; j++) {
            const int nb = wc * 64 + j * 8;
            bf[j][0] = Kt[nb + gm][kk + kq];
            bf[j][1] = Kt[nb + gm][kk + kq + 4];
        }
#pragma unroll
        for (int i = 0; i < 2; i++)
#pragma unroll
            for (int j = 0; j < 8; j++) mma8(acc[i][j], af[i], bf[j]);
    }

    float* outb = att + (size_t)(h * B_ + b) * L_ * L_;
    const unsigned char* mb = mask + (size_t)b * L_ * L_;
#pragma unroll
    for (int i = 0; i < 2; i++)
#pragma unroll
        for (int j = 0; j < 8; j++) {
            const int q = q0 + wr * 32 + i * 16 + gm;
            const int k = n0 + wc * 64 + j * 8 + kq * 2;
            float2 o0, o1;
            o0.x = mb[(size_t)q * L_ + k]           ? -INFINITY : acc[i][j][0] * 0.125f;
            o0.y = mb[(size_t)q * L_ + k + 1]       ? -INFINITY : acc[i][j][1] * 0.125f;
            o1.x = mb[(size_t)(q + 8) * L_ + k]     ? -INFINITY : acc[i][j][2] * 0.125f;
            o1.y = mb[(size_t)(q + 8) * L_ + k + 1] ? -INFINITY : acc[i][j][3] * 0.125f;
            *(float2*)(outb + (size_t)q * L_ + k)       = o0;
            *(float2*)(outb + (size_t)(q + 8) * L_ + k) = o1;
        }
}

// -------------- softmax over rows, in place; stores tf32-rounded -----------------
__global__ __launch_bounds__(256) void softmax_kernel(float* __restrict__ att)
{
    __shared__ float red[8];
    float* row = att + (size_t)blockIdx.x * L_;
    const int tid = threadIdx.x;
    float v[8];
#pragma unroll
    for (int i = 0; i < 8; i++) v[i] = row[tid + 256 * i];

    float m = -INFINITY;
#pragma unroll
    for (int i = 0; i < 8; i++) m = fmaxf(m, v[i]);
#pragma unroll
    for (int o = 16; o; o >>= 1) m = fmaxf(m, __shfl_xor_sync(0xffffffffu, m, o));
    if ((tid & 31) == 0) red[tid >> 5] = m;
    __syncthreads();
    m = red[0];
#pragma unroll
    for (int w = 1; w < 8; w++) m = fmaxf(m, red[w]);
    __syncthreads();

    float s = 0.f;
#pragma unroll
    for (int i = 0; i < 8; i++) { v[i] = __expf(v[i] - m); s += v[i]; }
#pragma unroll
    for (int o = 16; o; o >>= 1) s += __shfl_xor_sync(0xffffffffu, s, o);
    if ((tid & 31) == 0) red[tid >> 5] = s;
    __syncthreads();
    s = red[0];
#pragma unroll
    for (int w = 1; w < 8; w++) s += red[w];

    const float inv = 1.0f / s;
#pragma unroll
    for (int i = 0; i < 8; i++) row[tid + 256 * i] = rndtf(v[i] * inv);
}

// ============ PV: AO[b,q,h,:] = P[b,h,q,:] @ Vh[2048,64] ========================
// P (softmax out) and Vs pre-rounded. BK=32, cp.async double buffered.
#define PTS 36
#define VTS 72
__global__ __launch_bounds__(256, 2) void pv_tf32(
    const float* __restrict__ att, const float* __restrict__ Vs,
    float* __restrict__ AO)
{
    extern __shared__ unsigned sm[];
    // layout: Pt[2][128][36] then Vt[2][32][72]
    unsigned (*Pt)[128][PTS] = (unsigned(*)[128][PTS])sm;
    unsigned (*Vt)[32][VTS]  = (unsigned(*)[32][VTS])(sm + 2 * 128 * PTS);

    const int tid  = threadIdx.x;
    const int lane = tid & 31, warp = tid >> 5;
    const int wr = warp >> 1, wc = warp & 1;
    const int gm = lane >> 2, kq = lane & 3;
    const int bh = blockIdx.y;
    const int b = bh >> 4, h = bh & 15;
    const int q0 = blockIdx.x * 128;

    const float* Pb = att + (size_t)(h * B_ + b) * L_ * L_;
    const float* Vb = Vs + (size_t)b * L_ * HD_ + (size_t)h * DK_;
    const int prow = tid >> 1, pcb = (tid & 1) * 16;
    const int vrow = tid >> 3, vcb = (tid & 7) * 8;

    float acc[2][4][4];
#pragma unroll
    for (int i = 0; i < 2; i++)
#pragma unroll
        for (int j = 0; j < 4; j++)
#pragma unroll
            for (int r = 0; r < 4; r++) acc[i][j][r] = 0.f;

    auto load = [&](int buf, int k0) {
#pragma unroll
        for (int u = 0; u < 4; u++)
            cp16(&Pt[buf][prow][pcb + u * 4],
                 Pb + (size_t)(q0 + prow) * L_ + k0 + pcb + u * 4);
#pragma unroll
        for (int u = 0; u < 2; u++)
            cp16(&Vt[buf][vrow][vcb + u * 4],
                 Vb + (size_t)(k0 + vrow) * HD_ + vcb + u * 4);
    };

    load(0, 0); cpcommit();
    int buf = 0;
    for (int k0 = 0; k0 < L_; k0 += 32) {
        cpwait0();
        __syncthreads();
        if (k0 + 32 < L_) { load(buf ^ 1, k0 + 32); cpcommit(); }
#pragma unroll
        for (int kk = 0; kk < 32; kk += 8) {
            unsigned af[2][4], bf[4][2];
#pragma unroll
            for (int i = 0; i < 2; i++) {
                const int mb = wr * 32 + i * 16;
                af[i][0] = Pt[buf][mb + gm    ][kk + kq];
                af[i][1] = Pt[buf][mb + gm + 8][kk + kq];
                af[i][2] = Pt[buf][mb + gm    ][kk + kq + 4];
                af[i][3] = Pt[buf][mb + gm + 8][kk + kq + 4];
            }
#pragma unroll
            for (int j = 0; j < 4; j++) {
                const int nb = wc * 32 + j * 8;
                bf[j][0] = Vt[buf][kk + kq    ][nb + gm];
                bf[j][1] = Vt[buf][kk + kq + 4][nb + gm];
            }
#pragma unroll
            for (int i = 0; i < 2; i++)
#pragma unroll
                for (int j = 0; j < 4; j++) mma8(acc[i][j], af[i], bf[j]);
        }
        __syncthreads();
        buf ^= 1;
    }

#pragma unroll
    for (int i = 0; i < 2; i++)
#pragma unroll
        for (int j = 0; j < 4; j++) {
            const int q = q0 + wr * 32 + i * 16 + gm;
            const int col = wc * 32 + j * 8 + kq * 2;
            float2 o0, o1;
            o0.x = rndtf(acc[i][j][0]); o0.y = rndtf(acc[i][j][1]);
            o1.x = rndtf(acc[i][j][2]); o1.y = rndtf(acc[i][j][3]);
            *(float2*)(AO + (size_t)(b * L_ + q) * HD_ + h * DK_ + col)      = o0;
            *(float2*)(AO + (size_t)(b * L_ + q + 8) * HD_ + h * DK_ + col) = o1;
        }
}

// ---------------- residual + LayerNorm: y = LN(X + Q)*gamma + beta ---------------
__global__ __launch_bounds__(256) void ln_kernel(
    const float* __restrict__ X, const float* __restrict__ Qin,
    const float* __restrict__ gamma, const float* __restrict__ beta,
    float* __restrict__ y)
{
    __shared__ float red[8];
    const int row = blockIdx.x;
    const int tid = threadIdx.x;
    const float* xr = X + (size_t)row * DX_;
    const float* qr = Qin + (size_t)row * DX_;

    float x[4];
#pragma unroll
    for (int i = 0; i < 4; i++) x[i] = xr[tid + 256 * i] + qr[tid + 256 * i];

    float s = x[0] + x[1] + x[2] + x[3];
#pragma unroll
    for (int o = 16; o; o >>= 1) s += __shfl_xor_sync(0xffffffffu, s, o);
    if ((tid & 31) == 0) red[tid >> 5] = s;
    __syncthreads();
    s = red[0];
#pragma unroll
    for (int w = 1; w < 8; w++) s += red[w];
    const float mu = s * (1.0f / DX_);
    __syncthreads();

    float vs = 0.f;
#pragma unroll
    for (int i = 0; i < 4; i++) { float d = x[i] - mu; vs += d * d; }
#pragma unroll
    for (int o = 16; o; o >>= 1) vs += __shfl_xor_sync(0xffffffffu, vs, o);
    if ((tid & 31) == 0) red[tid >> 5] = vs;
    __syncthreads();
    vs = red[0];
#pragma unroll
    for (int w = 1; w < 8; w++) vs += red[w];
    const float var = vs * (1.0f / DX_);
    const float rs = rsqrtf(var + EPS_);

#pragma unroll
    for (int i = 0; i < 4; i++) {
        const int c = tid + 256 * i;
        y[(size_t)row * DX_ + c] = (x[i] - mu) * rs * gamma[c] + beta[c];
    }
}

// --------------------------------- launch ---------------------------------------
extern "C" void kernel_launch(void* const* d_in, const int* in_sizes, int n_in,
                              void* d_out, int out_size)
{
    const float* Q  = (const float*)d_in[0];
    const float* K  = (const float*)d_in[1];
    const float* V  = (const float*)d_in[2];
    const unsigned char* mask = (const unsigned char*)d_in[3];
    const float* Wq = (const float*)d_in[4];
    const float* bq = (const float*)d_in[5];
    const float* Wk = (const float*)d_in[6];
    const float* bk = (const float*)d_in[7];
    const float* Wv = (const float*)d_in[8];
    const float* bv = (const float*)d_in[9];
    const float* Wo = (const float*)d_in[10];
    const float* bo = (const float*)d_in[11];
    const float* gamma = (const float*)d_in[12];
    const float* beta  = (const float*)d_in[13];

    float* y   = (float*)d_out;
    float* att = (float*)d_out + (size_t)B_ * L_ * DX_;

    static float *pQs=nullptr,*pKs=nullptr,*pVs=nullptr,*pAO=nullptr,*pX=nullptr;
    static float *prQ=nullptr,*prK=nullptr,*prV=nullptr;
    static float *prWq=nullptr,*prWk=nullptr,*prWv=nullptr,*prWo=nullptr;
    if (!pQs) {
        cudaGetSymbolAddress((void**)&pQs, g_Qs);
        cudaGetSymbolAddress((void**)&pKs, g_Ks);
        cudaGetSymbolAddress((void**)&pVs, g_Vs);
        cudaGetSymbolAddress((void**)&pAO, g_AO);
        cudaGetSymbolAddress((void**)&pX,  g_X);
        cudaGetSymbolAddress((void**)&prQ, g_rQ);
        cudaGetSymbolAddress((void**)&prK, g_rK);
        cudaGetSymbolAddress((void**)&prV, g_rV);
        cudaGetSymbolAddress((void**)&prWq, g_rWq);
        cudaGetSymbolAddress((void**)&prWk, g_rWk);
        cudaGetSymbolAddress((void**)&prWv, g_rWv);
        cudaGetSymbolAddress((void**)&prWo, g_rWo);
    }

    cudaFuncSetAttribute(scores_tf32, cudaFuncAttributeMaxDynamicSharedMemorySize,
                         2 * 128 * SCS * 4);
    cudaFuncSetAttribute(pv_tf32, cudaFuncAttributeMaxDynamicSharedMemorySize,
                         (2 * 128 * PTS + 2 * 32 * VTS) * 4);

    const int nBig = B_ * L_ * DX_ / 4;     // float4 count for activations
    const int nW   = DX_ * HD_ / 4;         // float4 count for weights
    round_tf32<<<nBig / 256, 256>>>((const float4*)Q, (float4*)prQ, nBig);
    round_tf32<<<nBig / 256, 256>>>((const float4*)K, (float4*)prK, nBig);
    round_tf32<<<nBig / 256, 256>>>((const float4*)V, (float4*)prV, nBig);
    round_tf32<<<nW / 256, 256>>>((const float4*)Wq, (float4*)prWq, nW);
    round_tf32<<<nW / 256, 256>>>((const float4*)Wk, (float4*)prWk, nW);
    round_tf32<<<nW / 256, 256>>>((const float4*)Wv, (float4*)prWv, nW);
    round_tf32<<<nW / 256, 256>>>((const float4*)Wo, (float4*)prWo, nW);

    const dim3 gProj(HD_ / 128, (B_ * L_) / 128);   // (8, 64)

    sgemm_tf32<true><<<gProj, 256>>>(prQ, prWq, bq, pQs, B_ * L_, HD_, DX_);
    sgemm_tf32<true><<<gProj, 256>>>(prK, prWk, bk, pKs, B_ * L_, HD_, DX_);
    sgemm_tf32<true><<<gProj, 256>>>(prV, prWv, bv, pVs, B_ * L_, HD_, DX_);

    scores_tf32<<<dim3(L_ / 128, L_ / 128, B_ * H_), 256, 2 * 128 * SCS * 4>>>(
        pQs, pKs, mask, att);
    softmax_kernel<<<B_ * H_ * L_, 256>>>(att);
    pv_tf32<<<dim3(L_ / 128, B_ * H_), 256, (2 * 128 * PTS + 2 * 32 * VTS) * 4>>>(
        att, pVs, pAO);

    sgemm_tf32<false><<<gProj, 256>>>(pAO, prWo, bo, pX, B_ * L_, DX_, HD_);
    ln_kernel<<<B_ * L_, 256>>>(pX, Q, gamma, beta, y);
}